// round 1
// baseline (speedup 1.0000x reference)
#include <cuda_runtime.h>
#include <math.h>

// Problem constants
#define C32    32
#define HW     224
#define BATCH  16
#define NTAPS  288              // 32 ci * 3 * 3
#define TILE_Y 8
#define TILE_X 32
#define SX_H   10               // TILE_Y + 2 halo
#define SX_W   34               // TILE_X + 2 halo

// Scratch (static device globals; no runtime allocation)
__device__ float g_h[(size_t)BATCH * C32 * HW * HW];   // intermediate h (levels as float)
__device__ float g_w1t[NTAPS * C32];                   // conv1 signed weights, [tap][co]
__device__ float g_w2t[NTAPS * C32];                   // conv2 signed weights, [tap][co]
__device__ float g_t0[64];                             // per-channel threshold base (lut1 | lut2)
__device__ float g_dd[64];                             // per-channel threshold step

// ---------------------------------------------------------------------------
// Binarize weights: per output channel, subtract mean over 288 elems, take sign.
// (Division by std does not change the sign; jnp.sign(0)==0 preserved.)
// Writes transposed layout wt[tap*32 + co] so the conv kernel reads co-contiguous.
// One block per co, 128 threads.
// ---------------------------------------------------------------------------
__global__ void binarize_kernel(const float* __restrict__ w, float* __restrict__ wt) {
    int co = blockIdx.x;
    int t  = threadIdx.x;  // 0..127
    __shared__ float red[128];
    const float* wc = w + co * NTAPS;

    float v0 = wc[t];
    float v1 = wc[t + 128];
    float v2 = (t < 32) ? wc[t + 256] : 0.0f;
    red[t] = v0 + v1 + v2;
    __syncthreads();
    #pragma unroll
    for (int s = 64; s > 0; s >>= 1) {
        if (t < s) red[t] += red[t + s];
        __syncthreads();
    }
    float mean = red[0] / 288.0f;

    // sign(w - mean), with exact-zero -> 0 (matches jnp.sign)
    {
        float d = v0 - mean;
        wt[t * C32 + co] = (d > 0.0f) ? 1.0f : ((d < 0.0f) ? -1.0f : 0.0f);
    }
    {
        float d = v1 - mean;
        wt[(t + 128) * C32 + co] = (d > 0.0f) ? 1.0f : ((d < 0.0f) ? -1.0f : 0.0f);
    }
    if (t < 32) {
        float d = v2 - mean;
        wt[(t + 256) * C32 + co] = (d > 0.0f) ? 1.0f : ((d < 0.0f) ? -1.0f : 0.0f);
    }
}

// ---------------------------------------------------------------------------
// Build LUT thresholds. lut_j = rint(((j+0.5)*a2 - b) / (a1*w)), w = bn_w/sqrt(var+eps),
// b = bn_b - w*bn_mean. Forward only needs t0 = lut_0 and diff = lut_1 - lut_0
// (reference recomputes t_j = t0 + j*diff). rintf = round-half-even = jnp.round.
// threads 0..31 -> conv1 LUT (bn1, alpha1, alpha2); 32..63 -> conv2 LUT (bn2, alpha2, next_scale).
// ---------------------------------------------------------------------------
__global__ void lut_kernel(const float* __restrict__ bw1, const float* __restrict__ bb1,
                           const float* __restrict__ bm1, const float* __restrict__ bv1,
                           const float* __restrict__ bw2, const float* __restrict__ bb2,
                           const float* __restrict__ bm2, const float* __restrict__ bv2,
                           const float* __restrict__ a1p, const float* __restrict__ a2p,
                           const float* __restrict__ nsp) {
    int t = threadIdx.x;   // 0..63
    int c = t & 31;
    float w, b, s1, s2;
    if (t < 32) {
        w  = bw1[c] / sqrtf(bv1[c] + 1e-5f);
        b  = bb1[c] - w * bm1[c];
        s1 = a1p[0];
        s2 = a2p[0];
    } else {
        w  = bw2[c] / sqrtf(bv2[c] + 1e-5f);
        b  = bb2[c] - w * bm2[c];
        s1 = a2p[0];
        s2 = nsp[0];
    }
    float inv = 1.0f / (s1 * w);
    float l0 = rintf((0.5f * s2 - b) * inv);
    float l1 = rintf((1.5f * s2 - b) * inv);
    g_t0[t] = l0;
    g_dd[t] = l1 - l0;
}

// ---------------------------------------------------------------------------
// Fused 3x3 conv (pad 1, stride 1, ±1 weights as fp32) + LUT quantization.
// Block: 256 threads handles (batch b, 8x32 spatial tile, all 32 co).
// Thread: 4 co x 8 px register block -> 96 FMA per 13 LDS (FFMA-bound).
// smem: signed weights [288][32] (36.9 KB) + input halo tile [32][10][34] (43.5 KB).
// ---------------------------------------------------------------------------
__global__ __launch_bounds__(256, 2)
void conv_lut_kernel(const float* __restrict__ in, const float* __restrict__ wt,
                     const float* __restrict__ t0p, const float* __restrict__ ddp,
                     float* __restrict__ out) {
    extern __shared__ float sm[];
    float* s_w = sm;                 // NTAPS*32 = 9216 floats
    float* s_x = sm + NTAPS * C32;   // 32*10*34 = 10880 floats

    int tid = threadIdx.x;
    int b   = blockIdx.z;
    int y0  = blockIdx.y * TILE_Y;
    int x0  = blockIdx.x * TILE_X;

    // Stage weights
    #pragma unroll
    for (int i = tid; i < NTAPS * C32; i += 256) s_w[i] = wt[i];

    // Stage input tile with halo (zero padding)
    const float* inb = in + (size_t)b * C32 * HW * HW;
    for (int i = tid; i < C32 * SX_H * SX_W; i += 256) {
        int ci  = i / (SX_H * SX_W);
        int rem = i % (SX_H * SX_W);
        int ry  = rem / SX_W;
        int cx  = rem % SX_W;
        int gy  = y0 - 1 + ry;
        int gx  = x0 - 1 + cx;
        float v = 0.0f;
        if ((unsigned)gy < (unsigned)HW && (unsigned)gx < (unsigned)HW)
            v = inb[(ci * HW + gy) * HW + gx];
        s_x[i] = v;
    }
    __syncthreads();

    int g   = tid & 7;          // co group 0..7
    int p   = tid >> 3;         // 0..31
    int r   = p >> 2;           // tile row 0..7
    int xc  = (p & 3) * 8;      // tile col chunk {0,8,16,24}
    int co0 = g * 4;

    float acc[4][8];
    #pragma unroll
    for (int c = 0; c < 4; c++)
        #pragma unroll
        for (int k = 0; k < 8; k++) acc[c][k] = 0.0f;

    for (int ci = 0; ci < C32; ci++) {
        #pragma unroll
        for (int dy = 0; dy < 3; dy++) {
            const float* xr = &s_x[(ci * SX_H + r + dy) * SX_W + xc];
            float xv[10];
            #pragma unroll
            for (int k = 0; k < 10; k++) xv[k] = xr[k];
            #pragma unroll
            for (int dx = 0; dx < 3; dx++) {
                float4 w4 = *(const float4*)&s_w[((ci * 3 + dy) * 3 + dx) * C32 + co0];
                float wv[4] = {w4.x, w4.y, w4.z, w4.w};
                #pragma unroll
                for (int c = 0; c < 4; c++)
                    #pragma unroll
                    for (int k = 0; k < 8; k++)
                        acc[c][k] = fmaf(wv[c], xv[k + dx], acc[c][k]);
            }
        }
    }

    // LUT quantize + store (two float4 stores per co)
    #pragma unroll
    for (int c = 0; c < 4; c++) {
        int co   = co0 + c;
        float t0 = t0p[co];
        float dd = ddp[co];
        float res[8];
        #pragma unroll
        for (int k = 0; k < 8; k++) {
            float v  = acc[c][k];
            int lvl  = 0;
            #pragma unroll
            for (int j = 0; j < 7; j++) {
                float th = t0 + (float)j * dd;   // exact: integer thresholds
                lvl += (j & 1) ? (v >= th) : (v > th);   // match reference >/>= alternation
            }
            res[k] = (float)lvl;
        }
        float* op = out + ((((size_t)b * C32 + co) * HW) + (y0 + r)) * HW + x0 + xc;
        *(float4*)(op + 0) = make_float4(res[0], res[1], res[2], res[3]);
        *(float4*)(op + 4) = make_float4(res[4], res[5], res[6], res[7]);
    }
}

// ---------------------------------------------------------------------------
// Host launcher
// ---------------------------------------------------------------------------
extern "C" void kernel_launch(void* const* d_in, const int* in_sizes, int n_in,
                              void* d_out, int out_size) {
    const float* x   = (const float*)d_in[0];
    const float* w1  = (const float*)d_in[1];
    const float* w2  = (const float*)d_in[2];
    const float* bw1 = (const float*)d_in[3];
    const float* bb1 = (const float*)d_in[4];
    const float* bm1 = (const float*)d_in[5];
    const float* bv1 = (const float*)d_in[6];
    const float* bw2 = (const float*)d_in[7];
    const float* bb2 = (const float*)d_in[8];
    const float* bm2 = (const float*)d_in[9];
    const float* bv2 = (const float*)d_in[10];
    const float* a1  = (const float*)d_in[11];
    const float* a2  = (const float*)d_in[12];
    const float* ns  = (const float*)d_in[13];

    float *hbuf, *w1t, *w2t, *t0, *dd;
    cudaGetSymbolAddress((void**)&hbuf, g_h);
    cudaGetSymbolAddress((void**)&w1t,  g_w1t);
    cudaGetSymbolAddress((void**)&w2t,  g_w2t);
    cudaGetSymbolAddress((void**)&t0,   g_t0);
    cudaGetSymbolAddress((void**)&dd,   g_dd);

    const int smem_bytes = (NTAPS * C32 + C32 * SX_H * SX_W) * sizeof(float);  // 80384
    cudaFuncSetAttribute(conv_lut_kernel, cudaFuncAttributeMaxDynamicSharedMemorySize, smem_bytes);

    binarize_kernel<<<32, 128>>>(w1, w1t);
    binarize_kernel<<<32, 128>>>(w2, w2t);
    lut_kernel<<<1, 64>>>(bw1, bb1, bm1, bv1, bw2, bb2, bm2, bv2, a1, a2, ns);

    dim3 grid(HW / TILE_X, HW / TILE_Y, BATCH);  // (7, 28, 16)
    conv_lut_kernel<<<grid, 256, smem_bytes>>>(x,    w1t, t0,      dd,      hbuf);
    conv_lut_kernel<<<grid, 256, smem_bytes>>>(hbuf, w2t, t0 + 32, dd + 32, (float*)d_out);
}